// round 12
// baseline (speedup 1.0000x reference)
#include <cuda_runtime.h>
#include <cuda_fp16.h>
#include <cstdint>

// out[b,o,t,n] = relu( sum_{i,k,m} theta[i,o,k] x[b,i,t,m] G[k,n,m] + bias[o] + x[b,o,t,n] )
// B=8, C=64, T=12, N=4096, KS=3. r' = bt*64+o in [0,6144). K_total = 3*4096 = 12288 (192 chunks of 64).
// All tensor math via mma.sync (HMMA) -- tcgen05 unavailable (PTX target compute_103, no 'a').

#define KCH 192

// A tiles (Z): [mt 48][kc 192][128 rows x 64 halfs], SW128-swizzled rows. 151 MB.
__device__ __align__(1024) __half g_zx[(size_t)48 * KCH * 8192];
// B tiles (G): [nt 16][kc 192][256 rows x 64 halfs], SW128-swizzled rows. 96 MB.
__device__ __align__(1024) __half g_bas[(size_t)16 * KCH * 16384];
// theta A-tile image: 192 rows x 64 halfs, SW128-swizzled. 24 KB.
__device__ __align__(1024) __half g_tha[192 * 64];

__device__ __forceinline__ uint32_t smem_u32(const void* p) {
    uint32_t a;
    asm("{ .reg .u64 t; cvta.to.shared.u64 t, %1; cvt.u32.u64 %0, t; }" : "=r"(a) : "l"(p));
    return a;
}
#define SWZ(x) ((x) ^ (((x) >> 3) & 0x70u))

#define MBAR_INIT(mb, c) asm volatile("mbarrier.init.shared.b64 [%0], %1;" :: "r"((uint32_t)(mb)), "r"((uint32_t)(c)) : "memory")
#define MBAR_ARRIVE(mb)  asm volatile("mbarrier.arrive.shared.b64 _, [%0];" :: "r"((uint32_t)(mb)) : "memory")
#define MBAR_EXTX(mb, by) asm volatile("mbarrier.arrive.expect_tx.shared.b64 _, [%0], %1;" :: "r"((uint32_t)(mb)), "r"((uint32_t)(by)) : "memory")
#define MBAR_WAIT(mb, ph) do { \
    asm volatile("{\n\t.reg .pred P;\n\tWL%=:\n\t" \
        "mbarrier.try_wait.parity.acquire.cta.shared::cta.b64 P, [%0], %1, 0x989680;\n\t" \
        "@P bra.uni WD%=;\n\tbra.uni WL%=;\n\tWD%=:\n\t}" :: "r"((uint32_t)(mb)), "r"((uint32_t)(ph)) : "memory"); \
} while (0)
#define FENCE_ASYNC() asm volatile("fence.proxy.async.shared::cta;" ::: "memory")

__device__ __forceinline__ void bulk_g2s(uint32_t dst, const void* src, uint32_t bytes, uint32_t mbar) {
    asm volatile("cp.async.bulk.shared::cluster.global.mbarrier::complete_tx::bytes [%0], [%1], %2, [%3];"
                 :: "r"(dst), "l"(src), "r"(bytes), "r"(mbar) : "memory");
}

#define LDSM_X4(r0, r1, r2, r3, addr) \
    asm volatile("ldmatrix.sync.aligned.m8n8.x4.shared.b16 {%0,%1,%2,%3}, [%4];" \
                 : "=r"(r0), "=r"(r1), "=r"(r2), "=r"(r3) : "r"(addr))

#define MMA16816(c, a, b0_, b1_) \
    asm volatile("mma.sync.aligned.m16n8k16.row.col.f32.f16.f16.f32 " \
                 "{%0,%1,%2,%3}, {%4,%5,%6,%7}, {%8,%9}, {%0,%1,%2,%3};" \
                 : "+f"((c)[0]), "+f"((c)[1]), "+f"((c)[2]), "+f"((c)[3]) \
                 : "r"((a)[0]), "r"((a)[1]), "r"((a)[2]), "r"((a)[3]), "r"(b0_), "r"(b1_))

// ---------------------------------------------------------------------------
// Pass 1: theta[i][o][k] -> A-tile image (rows k*64+o, col i, SW128). Tiny.
// ---------------------------------------------------------------------------
__global__ void __launch_bounds__(256) prep_theta_kernel(const float* __restrict__ th) {
    int e = blockIdx.x * 256 + threadIdx.x;          // 12288 elements, grid 48
    int k = e % 3, io = e / 3;
    int o = io & 63, i = io >> 6;
    *(__half*)((char*)g_tha + SWZ((uint32_t)(k * 64 + o) * 128 + (uint32_t)i * 2)) =
        __float2half_rn(th[e]);
}

// ---------------------------------------------------------------------------
// Pass 2 (fused): blocks [0,3072) = theta-mix; blocks [3072,52224) = G convert.
// The two halves are independent (mix: x,theta -> g_zx; convert: G -> g_bas)
// and have complementary bottlenecks (tensor/L2 vs DRAM) -> run concurrently.
// ---------------------------------------------------------------------------
#define MX_A 1024
#define MX_B (1024 + 24576)
#define MX_SMEM (1024 + 24576 + 16384)

__global__ void __launch_bounds__(256) pre_kernel(const float* __restrict__ g,
                                                  const float* __restrict__ x) {
    if (blockIdx.x >= 3072) {
        // ---- convert: G fp32 [k][n][m] -> fp16 pre-swizzled B tiles ----
        size_t e = ((size_t)(blockIdx.x - 3072) * 256 + threadIdx.x) << 2;
        float4 v = *(const float4*)(g + e);
        uint32_t m = (uint32_t)(e & 4095), n = (uint32_t)((e >> 12) & 4095), k = (uint32_t)(e >> 24);
        uint32_t kc = (k << 6) + (m >> 6);
        uint32_t off = SWZ(((n & 255) << 7) + ((m & 63) << 1));
        __half2 h0 = __floats2half2_rn(v.x, v.y), h1 = __floats2half2_rn(v.z, v.w);
        uint2 w = make_uint2(*(uint32_t*)&h0, *(uint32_t*)&h1);
        *(uint2*)((char*)g_bas + (((size_t)((n >> 8) * KCH + kc)) << 15) + off) = w;
        return;
    }

    // ---- mix: CTA = (bt, 128-wide m chunk). 8 warps (2M x 4N). ----
    extern __shared__ char smem[];
    uint32_t sb = smem_u32(smem);
    int tid = threadIdx.x, lane = tid & 31, wid = tid >> 5;
    int wm = wid >> 2, wn = wid & 3;
    int bt = blockIdx.x >> 5, m0 = (blockIdx.x & 31) << 7;
    int b = bt / 12, t = bt - 12 * b;

    if (tid == 0) MBAR_INIT(sb + 64, 1);
    FENCE_ASYNC();
    __syncthreads();
    if (tid == 0) {                               // theta tile: one bulk copy
        MBAR_EXTX(sb + 64, 24576);
        bulk_g2s(sb + MX_A, g_tha, 24576, sb + 64);
    }

    // x[b][i][t][m0+m] -> B tile rows m, cols i. Transpose in registers:
    // thread handles (m, 8 i-values), one conflict-free STS.128.
    const float* xb = x + ((size_t)b * 768 + t) * 4096 + m0;
#pragma unroll
    for (int it = 0; it < 4; it++) {
        int idx = tid + it * 256;                 // 0..1023
        int m = idx & 127, gq = idx >> 7;         // gq: i-octet 0..7
        float v[8];
#pragma unroll
        for (int di = 0; di < 8; di++)
            v[di] = xb[(size_t)(gq * 8 + di) * 49152 + m];
        __half2 h0 = __floats2half2_rn(v[0], v[1]);
        __half2 h1 = __floats2half2_rn(v[2], v[3]);
        __half2 h2 = __floats2half2_rn(v[4], v[5]);
        __half2 h3 = __floats2half2_rn(v[6], v[7]);
        uint4 w = make_uint4(*(uint32_t*)&h0, *(uint32_t*)&h1,
                             *(uint32_t*)&h2, *(uint32_t*)&h3);
        *(uint4*)(smem + MX_B + SWZ((uint32_t)m * 128 + (uint32_t)gq * 16)) = w;
    }
    __syncthreads();
    MBAR_WAIT(sb + 64, 0);

    float c[6][4][4];
#pragma unroll
    for (int mi = 0; mi < 6; mi++)
#pragma unroll
        for (int ni = 0; ni < 4; ni++)
#pragma unroll
            for (int q = 0; q < 4; q++) c[mi][ni][q] = 0.f;

    uint32_t lrow = lane & 15, lcg = (uint32_t)(lane >> 4) << 4;
#pragma unroll
    for (int ks = 0; ks < 4; ks++) {
        uint32_t colb = (uint32_t)ks * 32 + lcg;
        uint32_t a[6][4], bf[2][4];
#pragma unroll
        for (int mi = 0; mi < 6; mi++) {
            uint32_t ad = sb + MX_A + SWZ((uint32_t)(wm * 96 + mi * 16 + lrow) * 128 + colb);
            LDSM_X4(a[mi][0], a[mi][1], a[mi][2], a[mi][3], ad);
        }
#pragma unroll
        for (int nj = 0; nj < 2; nj++) {
            uint32_t ad = sb + MX_B + SWZ((uint32_t)(wn * 32 + nj * 16 + lrow) * 128 + colb);
            LDSM_X4(bf[nj][0], bf[nj][1], bf[nj][2], bf[nj][3], ad);
        }
#pragma unroll
        for (int mi = 0; mi < 6; mi++)
#pragma unroll
            for (int ni = 0; ni < 4; ni++)
                MMA16816(c[mi][ni], a[mi], bf[ni >> 1][ni & 1], bf[ni >> 1][(ni & 1) + 2]);
    }

    char* gz = (char*)g_zx;
    uint32_t mt = (uint32_t)(bt >> 1);
    uint32_t rbase = (uint32_t)(bt & 1) << 6;
#pragma unroll
    for (int mi = 0; mi < 6; mi++) {
#pragma unroll
        for (int h = 0; h < 2; h++) {
            uint32_t ko = (uint32_t)(wm * 96 + mi * 16 + h * 8) + (uint32_t)(lane >> 2);
            uint32_t k = ko >> 6, o = ko & 63;
            uint32_t row = rbase + o;
#pragma unroll
            for (int ni = 0; ni < 4; ni++) {
                uint32_t m = (uint32_t)(m0 + wn * 32 + ni * 8) + (uint32_t)((lane & 3) << 1);
                uint32_t kc = k * 64 + (m >> 6);
                __half2 hv = __floats2half2_rn(c[mi][ni][2 * h], c[mi][ni][2 * h + 1]);
                *(uint32_t*)(gz + (((size_t)(mt * KCH + kc)) << 14) +
                             SWZ(row * 128 + ((m & 63) << 1))) = *(uint32_t*)&hv;
            }
        }
    }
}

// ---------------------------------------------------------------------------
// Pass 3: GEMM 6144x4096x12288 fp16->fp32 + fused epilogue (round-8 best).
// BM=128 BN=256 BK=64, 4 stages, 16 consumer warps (32x64) + 1 producer.
// ---------------------------------------------------------------------------
#define G_STG 49152
#define G_SMEM (1024 + 4 * G_STG)

__global__ void __launch_bounds__(544, 1) gemm_kernel(const float* __restrict__ x,
                                                      const float* __restrict__ bias,
                                                      float* __restrict__ out) {
    extern __shared__ char smem[];
    uint32_t sb = smem_u32(smem);
    int tid = threadIdx.x, lane = tid & 31, wid = tid >> 5;
    int id = blockIdx.x;
    int mt = (id >> 7) * 8 + (id & 7);     // 48 mtiles, groups of 8x16
    int nt = (id & 127) >> 3;              // 16 ntiles

    if (tid == 0) {
#pragma unroll
        for (int s = 0; s < 4; s++) {
            MBAR_INIT(sb + 16 * s, 1);        // full (tx-based)
            MBAR_INIT(sb + 16 * s + 8, 16);   // empty (16 consumer warps)
        }
    }
    FENCE_ASYNC();
    __syncthreads();

    if (wid == 16) {                          // producer warp
        if (lane == 0) {
            const char* As = (const char*)g_zx + ((size_t)mt * KCH << 14);
            const char* Bs = (const char*)g_bas + ((size_t)nt * KCH << 15);
            for (int cc = 0; cc < KCH; cc++) {
                int s = cc & 3;
                if (cc >= 4) MBAR_WAIT(sb + 16 * s + 8, ((cc >> 2) + 1) & 1);
                MBAR_EXTX(sb + 16 * s, G_STG);
                uint32_t dst = sb + 1024 + s * G_STG;
                bulk_g2s(dst, As + ((size_t)cc << 14), 16384, sb + 16 * s);
                bulk_g2s(dst + 16384, Bs + ((size_t)cc << 15), 32768, sb + 16 * s);
            }
        }
        return;
    }

    // 16 consumer warps: warp tile 32 (rows) x 64 (cols)
    int wm = wid >> 2, wn = wid & 3;
    uint32_t lrow = lane & 15, lcg = (uint32_t)(lane >> 4) << 4;
    uint32_t aoff[2], boff[4];
#pragma unroll
    for (int mi = 0; mi < 2; mi++)
        aoff[mi] = (uint32_t)(wm * 32 + mi * 16 + lrow) * 128;
#pragma unroll
    for (int nj = 0; nj < 4; nj++)
        boff[nj] = 16384u + (uint32_t)(wn * 64 + nj * 16 + lrow) * 128;
    uint32_t swa = ((lrow & 7) << 4);

    float c[2][8][4];
#pragma unroll
    for (int mi = 0; mi < 2; mi++)
#pragma unroll
        for (int ni = 0; ni < 8; ni++)
#pragma unroll
            for (int q = 0; q < 4; q++) c[mi][ni][q] = 0.f;

#pragma unroll 1
    for (int cc = 0; cc < KCH; cc++) {
        int s = cc & 3;
        MBAR_WAIT(sb + 16 * s, (cc >> 2) & 1);
        uint32_t stg = sb + 1024 + s * G_STG;
#pragma unroll
        for (int ks = 0; ks < 4; ks++) {
            uint32_t colb = ((uint32_t)ks * 32 + lcg) ^ swa;
            uint32_t a[2][4], bf[4][4];
#pragma unroll
            for (int mi = 0; mi < 2; mi++)
                LDSM_X4(a[mi][0], a[mi][1], a[mi][2], a[mi][3], stg + aoff[mi] + colb);
#pragma unroll
            for (int nj = 0; nj < 4; nj++)
                LDSM_X4(bf[nj][0], bf[nj][1], bf[nj][2], bf[nj][3], stg + boff[nj] + colb);
#pragma unroll
            for (int mi = 0; mi < 2; mi++)
#pragma unroll
                for (int ni = 0; ni < 8; ni++)
                    MMA16816(c[mi][ni], a[mi], bf[ni >> 1][ni & 1], bf[ni >> 1][(ni & 1) + 2]);
        }
        __syncwarp();
        if (lane == 0) MBAR_ARRIVE(sb + 16 * s + 8);
    }

    // fused epilogue: bias + identity residual + relu
#pragma unroll
    for (int mi = 0; mi < 2; mi++) {
#pragma unroll
        for (int h = 0; h < 2; h++) {
            uint32_t r = (uint32_t)(mt * 128 + wm * 32 + mi * 16 + h * 8) + (uint32_t)(lane >> 2);
            uint32_t bt = r >> 6, o = r & 63;
            uint32_t bb = bt / 12, tt = bt - 12 * bb;
            size_t base = ((size_t)((bb << 6) + o) * 12 + tt) * 4096;
            float bv = __ldg(bias + o);
#pragma unroll
            for (int ni = 0; ni < 8; ni++) {
                size_t col = (size_t)(nt * 256 + wn * 64 + ni * 8) + ((lane & 3) << 1);
                float2 xv = *(const float2*)(x + base + col);
                float2 ov;
                ov.x = fmaxf(c[mi][ni][2 * h + 0] + bv + xv.x, 0.f);
                ov.y = fmaxf(c[mi][ni][2 * h + 1] + bv + xv.y, 0.f);
                *(float2*)(out + base + col) = ov;
            }
        }
    }
}

// ---------------------------------------------------------------------------
extern "C" void kernel_launch(void* const* d_in, const int* in_sizes, int n_in,
                              void* d_out, int out_size) {
    const float* x = (const float*)d_in[0];
    const float* g = (const float*)d_in[1];
    const float* th = (const float*)d_in[2];
    const float* bias = (const float*)d_in[3];
    float* out = (float*)d_out;

    cudaFuncSetAttribute(gemm_kernel, cudaFuncAttributeMaxDynamicSharedMemorySize, G_SMEM);

    prep_theta_kernel<<<48, 256>>>(th);
    pre_kernel<<<52224, 256, MX_SMEM>>>(g, x);
    gemm_kernel<<<768, 544, G_SMEM>>>(x, bias, out);
}

// round 13
// speedup vs baseline: 1.0573x; 1.0573x over previous
#include <cuda_runtime.h>
#include <cuda_fp16.h>
#include <cstdint>

// out[b,o,t,n] = relu( sum_{i,k,m} theta[i,o,k] x[b,i,t,m] G[k,n,m] + bias[o] + x[b,o,t,n] )
// B=8, C=64, T=12, N=4096, KS=3. r' = bt*64+o in [0,6144). K_total = 3*4096 = 12288 (192 chunks of 64).
// All tensor math via mma.sync (HMMA) -- tcgen05 unavailable (PTX target compute_103, no 'a').

#define KCH 192

// A tiles (Z): [mt 48][kc 192][128 rows x 64 halfs], SW128-swizzled rows. 151 MB.
__device__ __align__(1024) __half g_zx[(size_t)48 * KCH * 8192];
// B tiles (G): [nt 16][kc 192][256 rows x 64 halfs], SW128-swizzled rows. 96 MB.
__device__ __align__(1024) __half g_bas[(size_t)16 * KCH * 16384];
// theta A-tile image: 192 rows x 64 halfs, SW128-swizzled. 24 KB.
__device__ __align__(1024) __half g_tha[192 * 64];

__device__ __forceinline__ uint32_t smem_u32(const void* p) {
    uint32_t a;
    asm("{ .reg .u64 t; cvta.to.shared.u64 t, %1; cvt.u32.u64 %0, t; }" : "=r"(a) : "l"(p));
    return a;
}
#define SWZ(x) ((x) ^ (((x) >> 3) & 0x70u))

#define MBAR_INIT(mb, c) asm volatile("mbarrier.init.shared.b64 [%0], %1;" :: "r"((uint32_t)(mb)), "r"((uint32_t)(c)) : "memory")
#define MBAR_ARRIVE(mb)  asm volatile("mbarrier.arrive.shared.b64 _, [%0];" :: "r"((uint32_t)(mb)) : "memory")
#define MBAR_EXTX(mb, by) asm volatile("mbarrier.arrive.expect_tx.shared.b64 _, [%0], %1;" :: "r"((uint32_t)(mb)), "r"((uint32_t)(by)) : "memory")
#define MBAR_WAIT(mb, ph) do { \
    asm volatile("{\n\t.reg .pred P;\n\tWL%=:\n\t" \
        "mbarrier.try_wait.parity.acquire.cta.shared::cta.b64 P, [%0], %1, 0x989680;\n\t" \
        "@P bra.uni WD%=;\n\tbra.uni WL%=;\n\tWD%=:\n\t}" :: "r"((uint32_t)(mb)), "r"((uint32_t)(ph)) : "memory"); \
} while (0)
#define FENCE_ASYNC() asm volatile("fence.proxy.async.shared::cta;" ::: "memory")

__device__ __forceinline__ void bulk_g2s(uint32_t dst, const void* src, uint32_t bytes, uint32_t mbar) {
    asm volatile("cp.async.bulk.shared::cluster.global.mbarrier::complete_tx::bytes [%0], [%1], %2, [%3];"
                 :: "r"(dst), "l"(src), "r"(bytes), "r"(mbar) : "memory");
}

#define LDSM_X4(r0, r1, r2, r3, addr) \
    asm volatile("ldmatrix.sync.aligned.m8n8.x4.shared.b16 {%0,%1,%2,%3}, [%4];" \
                 : "=r"(r0), "=r"(r1), "=r"(r2), "=r"(r3) : "r"(addr))

#define MMA16816(c, a, b0_, b1_) \
    asm volatile("mma.sync.aligned.m16n8k16.row.col.f32.f16.f16.f32 " \
                 "{%0,%1,%2,%3}, {%4,%5,%6,%7}, {%8,%9}, {%0,%1,%2,%3};" \
                 : "+f"((c)[0]), "+f"((c)[1]), "+f"((c)[2]), "+f"((c)[3]) \
                 : "r"((a)[0]), "r"((a)[1]), "r"((a)[2]), "r"((a)[3]), "r"(b0_), "r"(b1_))

// ---------------------------------------------------------------------------
// Pass 1a: G fp32 [k][n][m] -> fp16 pre-swizzled B tiles (standalone: 16 regs,
// high occupancy, DRAM-bound). Runs on forked stream, parallel with mix.
// ---------------------------------------------------------------------------
__global__ void __launch_bounds__(256) convert_kernel(const float* __restrict__ g) {
    size_t e = ((size_t)blockIdx.x * 256 + threadIdx.x) << 2;
    float4 v = *(const float4*)(g + e);
    uint32_t m = (uint32_t)(e & 4095), n = (uint32_t)((e >> 12) & 4095), k = (uint32_t)(e >> 24);
    uint32_t kc = (k << 6) + (m >> 6);
    uint32_t off = SWZ(((n & 255) << 7) + ((m & 63) << 1));
    __half2 h0 = __floats2half2_rn(v.x, v.y), h1 = __floats2half2_rn(v.z, v.w);
    uint2 w = make_uint2(*(uint32_t*)&h0, *(uint32_t*)&h1);
    *(uint2*)((char*)g_bas + (((size_t)((n >> 8) * KCH + kc)) << 15) + off) = w;
}

// ---------------------------------------------------------------------------
// Pass 1b: theta[i][o][k] -> A-tile image (rows k*64+o, col i, SW128). Tiny.
// ---------------------------------------------------------------------------
__global__ void __launch_bounds__(256) prep_theta_kernel(const float* __restrict__ th) {
    int e = blockIdx.x * 256 + threadIdx.x;          // 12288 elements, grid 48
    int k = e % 3, io = e / 3;
    int o = io & 63, i = io >> 6;
    *(__half*)((char*)g_tha + SWZ((uint32_t)(k * 64 + o) * 128 + (uint32_t)i * 2)) =
        __float2half_rn(th[e]);
}

// ---------------------------------------------------------------------------
// Pass 2: theta-mix. CTA = (bt, 128-wide m chunk). 256 threads, 8 warps (2M x 4N).
// ---------------------------------------------------------------------------
#define MX_A 1024
#define MX_B (1024 + 24576)
#define MX_SMEM (1024 + 24576 + 16384)

__global__ void __launch_bounds__(256) mix_kernel(const float* __restrict__ x) {
    extern __shared__ char smem[];
    uint32_t sb = smem_u32(smem);
    int tid = threadIdx.x, lane = tid & 31, wid = tid >> 5;
    int wm = wid >> 2, wn = wid & 3;
    int bt = blockIdx.x, m0 = blockIdx.y << 7;
    int b = bt / 12, t = bt - 12 * b;

    if (tid == 0) MBAR_INIT(sb + 64, 1);
    FENCE_ASYNC();
    __syncthreads();
    if (tid == 0) {                               // theta tile: one bulk copy
        MBAR_EXTX(sb + 64, 24576);
        bulk_g2s(sb + MX_A, g_tha, 24576, sb + 64);
    }

    // x[b][i][t][m0+m] -> B tile rows m, cols i. Transpose in registers:
    // thread handles (m, 8 i-values), one conflict-free STS.128.
    const float* xb = x + ((size_t)b * 768 + t) * 4096 + m0;
#pragma unroll
    for (int it = 0; it < 4; it++) {
        int idx = tid + it * 256;                 // 0..1023
        int m = idx & 127, gq = idx >> 7;         // gq: i-octet 0..7
        float v[8];
#pragma unroll
        for (int di = 0; di < 8; di++)
            v[di] = xb[(size_t)(gq * 8 + di) * 49152 + m];
        __half2 h0 = __floats2half2_rn(v[0], v[1]);
        __half2 h1 = __floats2half2_rn(v[2], v[3]);
        __half2 h2 = __floats2half2_rn(v[4], v[5]);
        __half2 h3 = __floats2half2_rn(v[6], v[7]);
        uint4 w = make_uint4(*(uint32_t*)&h0, *(uint32_t*)&h1,
                             *(uint32_t*)&h2, *(uint32_t*)&h3);
        *(uint4*)(smem + MX_B + SWZ((uint32_t)m * 128 + (uint32_t)gq * 16)) = w;
    }
    __syncthreads();
    MBAR_WAIT(sb + 64, 0);

    float c[6][4][4];
#pragma unroll
    for (int mi = 0; mi < 6; mi++)
#pragma unroll
        for (int ni = 0; ni < 4; ni++)
#pragma unroll
            for (int q = 0; q < 4; q++) c[mi][ni][q] = 0.f;

    uint32_t lrow = lane & 15, lcg = (uint32_t)(lane >> 4) << 4;
#pragma unroll
    for (int ks = 0; ks < 4; ks++) {
        uint32_t colb = (uint32_t)ks * 32 + lcg;
        uint32_t a[6][4], bf[2][4];
#pragma unroll
        for (int mi = 0; mi < 6; mi++) {
            uint32_t ad = sb + MX_A + SWZ((uint32_t)(wm * 96 + mi * 16 + lrow) * 128 + colb);
            LDSM_X4(a[mi][0], a[mi][1], a[mi][2], a[mi][3], ad);
        }
#pragma unroll
        for (int nj = 0; nj < 2; nj++) {
            uint32_t ad = sb + MX_B + SWZ((uint32_t)(wn * 32 + nj * 16 + lrow) * 128 + colb);
            LDSM_X4(bf[nj][0], bf[nj][1], bf[nj][2], bf[nj][3], ad);
        }
#pragma unroll
        for (int mi = 0; mi < 6; mi++)
#pragma unroll
            for (int ni = 0; ni < 4; ni++)
                MMA16816(c[mi][ni], a[mi], bf[ni >> 1][ni & 1], bf[ni >> 1][(ni & 1) + 2]);
    }

    char* gz = (char*)g_zx;
    uint32_t mt = (uint32_t)(bt >> 1);
    uint32_t rbase = (uint32_t)(bt & 1) << 6;
#pragma unroll
    for (int mi = 0; mi < 6; mi++) {
#pragma unroll
        for (int h = 0; h < 2; h++) {
            uint32_t ko = (uint32_t)(wm * 96 + mi * 16 + h * 8) + (uint32_t)(lane >> 2);
            uint32_t k = ko >> 6, o = ko & 63;
            uint32_t row = rbase + o;
#pragma unroll
            for (int ni = 0; ni < 4; ni++) {
                uint32_t m = (uint32_t)(m0 + wn * 32 + ni * 8) + (uint32_t)((lane & 3) << 1);
                uint32_t kc = k * 64 + (m >> 6);
                __half2 hv = __floats2half2_rn(c[mi][ni][2 * h], c[mi][ni][2 * h + 1]);
                *(uint32_t*)(gz + (((size_t)(mt * KCH + kc)) << 14) +
                             SWZ(row * 128 + ((m & 63) << 1))) = *(uint32_t*)&hv;
            }
        }
    }
}

// ---------------------------------------------------------------------------
// Pass 3: GEMM 6144x4096x12288 fp16->fp32 + fused epilogue (round-8 best).
// BM=128 BN=256 BK=64, 4 stages, 16 consumer warps (32x64) + 1 producer.
// ---------------------------------------------------------------------------
#define G_STG 49152
#define G_SMEM (1024 + 4 * G_STG)

__global__ void __launch_bounds__(544, 1) gemm_kernel(const float* __restrict__ x,
                                                      const float* __restrict__ bias,
                                                      float* __restrict__ out) {
    extern __shared__ char smem[];
    uint32_t sb = smem_u32(smem);
    int tid = threadIdx.x, lane = tid & 31, wid = tid >> 5;
    int id = blockIdx.x;
    int mt = (id >> 7) * 8 + (id & 7);     // 48 mtiles, groups of 8x16
    int nt = (id & 127) >> 3;              // 16 ntiles

    if (tid == 0) {
#pragma unroll
        for (int s = 0; s < 4; s++) {
            MBAR_INIT(sb + 16 * s, 1);        // full (tx-based)
            MBAR_INIT(sb + 16 * s + 8, 16);   // empty (16 consumer warps)
        }
    }
    FENCE_ASYNC();
    __syncthreads();

    if (wid == 16) {                          // producer warp
        if (lane == 0) {
            const char* As = (const char*)g_zx + ((size_t)mt * KCH << 14);
            const char* Bs = (const char*)g_bas + ((size_t)nt * KCH << 15);
            for (int cc = 0; cc < KCH; cc++) {
                int s = cc & 3;
                if (cc >= 4) MBAR_WAIT(sb + 16 * s + 8, ((cc >> 2) + 1) & 1);
                MBAR_EXTX(sb + 16 * s, G_STG);
                uint32_t dst = sb + 1024 + s * G_STG;
                bulk_g2s(dst, As + ((size_t)cc << 14), 16384, sb + 16 * s);
                bulk_g2s(dst + 16384, Bs + ((size_t)cc << 15), 32768, sb + 16 * s);
            }
        }
        return;
    }

    // 16 consumer warps: warp tile 32 (rows) x 64 (cols)
    int wm = wid >> 2, wn = wid & 3;
    uint32_t lrow = lane & 15, lcg = (uint32_t)(lane >> 4) << 4;
    uint32_t aoff[2], boff[4];
#pragma unroll
    for (int mi = 0; mi < 2; mi++)
        aoff[mi] = (uint32_t)(wm * 32 + mi * 16 + lrow) * 128;
#pragma unroll
    for (int nj = 0; nj < 4; nj++)
        boff[nj] = 16384u + (uint32_t)(wn * 64 + nj * 16 + lrow) * 128;
    uint32_t swa = ((lrow & 7) << 4);

    float c[2][8][4];
#pragma unroll
    for (int mi = 0; mi < 2; mi++)
#pragma unroll
        for (int ni = 0; ni < 8; ni++)
#pragma unroll
            for (int q = 0; q < 4; q++) c[mi][ni][q] = 0.f;

#pragma unroll 1
    for (int cc = 0; cc < KCH; cc++) {
        int s = cc & 3;
        MBAR_WAIT(sb + 16 * s, (cc >> 2) & 1);
        uint32_t stg = sb + 1024 + s * G_STG;
#pragma unroll
        for (int ks = 0; ks < 4; ks++) {
            uint32_t colb = ((uint32_t)ks * 32 + lcg) ^ swa;
            uint32_t a[2][4], bf[4][4];
#pragma unroll
            for (int mi = 0; mi < 2; mi++)
                LDSM_X4(a[mi][0], a[mi][1], a[mi][2], a[mi][3], stg + aoff[mi] + colb);
#pragma unroll
            for (int nj = 0; nj < 4; nj++)
                LDSM_X4(bf[nj][0], bf[nj][1], bf[nj][2], bf[nj][3], stg + boff[nj] + colb);
#pragma unroll
            for (int mi = 0; mi < 2; mi++)
#pragma unroll
                for (int ni = 0; ni < 8; ni++)
                    MMA16816(c[mi][ni], a[mi], bf[ni >> 1][ni & 1], bf[ni >> 1][(ni & 1) + 2]);
        }
        __syncwarp();
        if (lane == 0) MBAR_ARRIVE(sb + 16 * s + 8);
    }

    // fused epilogue: bias + identity residual + relu
#pragma unroll
    for (int mi = 0; mi < 2; mi++) {
#pragma unroll
        for (int h = 0; h < 2; h++) {
            uint32_t r = (uint32_t)(mt * 128 + wm * 32 + mi * 16 + h * 8) + (uint32_t)(lane >> 2);
            uint32_t bt = r >> 6, o = r & 63;
            uint32_t bb = bt / 12, tt = bt - 12 * bb;
            size_t base = ((size_t)((bb << 6) + o) * 12 + tt) * 4096;
            float bv = __ldg(bias + o);
#pragma unroll
            for (int ni = 0; ni < 8; ni++) {
                size_t col = (size_t)(nt * 256 + wn * 64 + ni * 8) + ((lane & 3) << 1);
                float2 xv = *(const float2*)(x + base + col);
                float2 ov;
                ov.x = fmaxf(c[mi][ni][2 * h + 0] + bv + xv.x, 0.f);
                ov.y = fmaxf(c[mi][ni][2 * h + 1] + bv + xv.y, 0.f);
                *(float2*)(out + base + col) = ov;
            }
        }
    }
}

// ---------------------------------------------------------------------------
// Launch: convert runs on a forked stream, concurrent with prep_theta + mix
// (disjoint outputs; complementary bottlenecks). Event fork/join is the
// documented multi-stream graph-capture pattern -- all captured ops are still
// kernel launches only. Streams/events created once (no device allocation).
// ---------------------------------------------------------------------------
extern "C" void kernel_launch(void* const* d_in, const int* in_sizes, int n_in,
                              void* d_out, int out_size) {
    const float* x = (const float*)d_in[0];
    const float* g = (const float*)d_in[1];
    const float* th = (const float*)d_in[2];
    const float* bias = (const float*)d_in[3];
    float* out = (float*)d_out;

    static cudaStream_t s2 = nullptr;
    static cudaEvent_t ev_fork = nullptr, ev_join = nullptr;
    if (s2 == nullptr) {
        cudaStreamCreateWithFlags(&s2, cudaStreamNonBlocking);
        cudaEventCreateWithFlags(&ev_fork, cudaEventDisableTiming);
        cudaEventCreateWithFlags(&ev_join, cudaEventDisableTiming);
        cudaFuncSetAttribute(gemm_kernel, cudaFuncAttributeMaxDynamicSharedMemorySize, G_SMEM);
    }

    // fork: convert on s2, concurrent with prep_theta + mix on the main stream
    cudaEventRecord(ev_fork, 0);
    cudaStreamWaitEvent(s2, ev_fork, 0);
    convert_kernel<<<49152, 256, 0, s2>>>(g);
    prep_theta_kernel<<<48, 256>>>(th);
    mix_kernel<<<dim3(96, 32), 256, MX_SMEM>>>(x);
    cudaEventRecord(ev_join, s2);
    cudaStreamWaitEvent(0, ev_join, 0);

    gemm_kernel<<<768, 544, G_SMEM>>>(x, bias, out);
}

// round 14
// speedup vs baseline: 1.0885x; 1.0295x over previous
#include <cuda_runtime.h>
#include <cuda_fp16.h>
#include <cstdint>

// out[b,o,t,n] = relu( sum_{i,k,m} theta[i,o,k] x[b,i,t,m] G[k,n,m] + bias[o] + x[b,o,t,n] )
// B=8, C=64, T=12, N=4096, KS=3. r' = bt*64+o in [0,6144). K_total = 3*4096 = 12288 (192 chunks of 64).
// All tensor math via mma.sync (HMMA) -- tcgen05 unavailable (PTX target compute_103, no 'a').

#define KCH 192

// A tiles (Z): [mt 48][kc 192][128 rows x 64 halfs], SW128-swizzled rows. 151 MB.
__device__ __align__(1024) __half g_zx[(size_t)48 * KCH * 8192];
// B tiles (G): [nt 16][kc 192][256 rows x 64 halfs], SW128-swizzled rows. 96 MB.
// (GEMM v2 treats it as 32 half-strips of 128 rows: nt2 = n>>7.)
__device__ __align__(1024) __half g_bas[(size_t)16 * KCH * 16384];
// theta A-tile image: 192 rows x 64 halfs, SW128-swizzled. 24 KB.
__device__ __align__(1024) __half g_tha[192 * 64];

__device__ __forceinline__ uint32_t smem_u32(const void* p) {
    uint32_t a;
    asm("{ .reg .u64 t; cvta.to.shared.u64 t, %1; cvt.u32.u64 %0, t; }" : "=r"(a) : "l"(p));
    return a;
}
#define SWZ(x) ((x) ^ (((x) >> 3) & 0x70u))

#define MBAR_INIT(mb, c) asm volatile("mbarrier.init.shared.b64 [%0], %1;" :: "r"((uint32_t)(mb)), "r"((uint32_t)(c)) : "memory")
#define MBAR_ARRIVE(mb)  asm volatile("mbarrier.arrive.shared.b64 _, [%0];" :: "r"((uint32_t)(mb)) : "memory")
#define MBAR_EXTX(mb, by) asm volatile("mbarrier.arrive.expect_tx.shared.b64 _, [%0], %1;" :: "r"((uint32_t)(mb)), "r"((uint32_t)(by)) : "memory")
#define MBAR_WAIT(mb, ph) do { \
    asm volatile("{\n\t.reg .pred P;\n\tWL%=:\n\t" \
        "mbarrier.try_wait.parity.acquire.cta.shared::cta.b64 P, [%0], %1, 0x989680;\n\t" \
        "@P bra.uni WD%=;\n\tbra.uni WL%=;\n\tWD%=:\n\t}" :: "r"((uint32_t)(mb)), "r"((uint32_t)(ph)) : "memory"); \
} while (0)
#define FENCE_ASYNC() asm volatile("fence.proxy.async.shared::cta;" ::: "memory")

__device__ __forceinline__ void bulk_g2s(uint32_t dst, const void* src, uint32_t bytes, uint32_t mbar) {
    asm volatile("cp.async.bulk.shared::cluster.global.mbarrier::complete_tx::bytes [%0], [%1], %2, [%3];"
                 :: "r"(dst), "l"(src), "r"(bytes), "r"(mbar) : "memory");
}

#define LDSM_X4(r0, r1, r2, r3, addr) \
    asm volatile("ldmatrix.sync.aligned.m8n8.x4.shared.b16 {%0,%1,%2,%3}, [%4];" \
                 : "=r"(r0), "=r"(r1), "=r"(r2), "=r"(r3) : "r"(addr))

#define MMA16816(c, a, b0_, b1_) \
    asm volatile("mma.sync.aligned.m16n8k16.row.col.f32.f16.f16.f32 " \
                 "{%0,%1,%2,%3}, {%4,%5,%6,%7}, {%8,%9}, {%0,%1,%2,%3};" \
                 : "+f"((c)[0]), "+f"((c)[1]), "+f"((c)[2]), "+f"((c)[3]) \
                 : "r"((a)[0]), "r"((a)[1]), "r"((a)[2]), "r"((a)[3]), "r"(b0_), "r"(b1_))

// ---------------------------------------------------------------------------
// Pass 1a: G fp32 [k][n][m] -> fp16 pre-swizzled B tiles (standalone).
// ---------------------------------------------------------------------------
__global__ void __launch_bounds__(256) convert_kernel(const float* __restrict__ g) {
    size_t e = ((size_t)blockIdx.x * 256 + threadIdx.x) << 2;
    float4 v = *(const float4*)(g + e);
    uint32_t m = (uint32_t)(e & 4095), n = (uint32_t)((e >> 12) & 4095), k = (uint32_t)(e >> 24);
    uint32_t kc = (k << 6) + (m >> 6);
    uint32_t off = SWZ(((n & 255) << 7) + ((m & 63) << 1));
    __half2 h0 = __floats2half2_rn(v.x, v.y), h1 = __floats2half2_rn(v.z, v.w);
    uint2 w = make_uint2(*(uint32_t*)&h0, *(uint32_t*)&h1);
    *(uint2*)((char*)g_bas + (((size_t)((n >> 8) * KCH + kc)) << 15) + off) = w;
}

// ---------------------------------------------------------------------------
// Pass 1b: theta[i][o][k] -> A-tile image (rows k*64+o, col i, SW128). Tiny.
// ---------------------------------------------------------------------------
__global__ void __launch_bounds__(256) prep_theta_kernel(const float* __restrict__ th) {
    int e = blockIdx.x * 256 + threadIdx.x;          // 12288 elements, grid 48
    int k = e % 3, io = e / 3;
    int o = io & 63, i = io >> 6;
    *(__half*)((char*)g_tha + SWZ((uint32_t)(k * 64 + o) * 128 + (uint32_t)i * 2)) =
        __float2half_rn(th[e]);
}

// ---------------------------------------------------------------------------
// Pass 2: theta-mix. CTA = (bt, 128-wide m chunk). 256 threads, 8 warps (2M x 4N).
// ---------------------------------------------------------------------------
#define MX_A 1024
#define MX_B (1024 + 24576)
#define MX_SMEM (1024 + 24576 + 16384)

__global__ void __launch_bounds__(256) mix_kernel(const float* __restrict__ x) {
    extern __shared__ char smem[];
    uint32_t sb = smem_u32(smem);
    int tid = threadIdx.x, lane = tid & 31, wid = tid >> 5;
    int wm = wid >> 2, wn = wid & 3;
    int bt = blockIdx.x, m0 = blockIdx.y << 7;
    int b = bt / 12, t = bt - 12 * b;

    if (tid == 0) MBAR_INIT(sb + 64, 1);
    FENCE_ASYNC();
    __syncthreads();
    if (tid == 0) {                               // theta tile: one bulk copy
        MBAR_EXTX(sb + 64, 24576);
        bulk_g2s(sb + MX_A, g_tha, 24576, sb + 64);
    }

    const float* xb = x + ((size_t)b * 768 + t) * 4096 + m0;
#pragma unroll
    for (int it = 0; it < 4; it++) {
        int idx = tid + it * 256;
        int m = idx & 127, gq = idx >> 7;
        float v[8];
#pragma unroll
        for (int di = 0; di < 8; di++)
            v[di] = xb[(size_t)(gq * 8 + di) * 49152 + m];
        __half2 h0 = __floats2half2_rn(v[0], v[1]);
        __half2 h1 = __floats2half2_rn(v[2], v[3]);
        __half2 h2 = __floats2half2_rn(v[4], v[5]);
        __half2 h3 = __floats2half2_rn(v[6], v[7]);
        uint4 w = make_uint4(*(uint32_t*)&h0, *(uint32_t*)&h1,
                             *(uint32_t*)&h2, *(uint32_t*)&h3);
        *(uint4*)(smem + MX_B + SWZ((uint32_t)m * 128 + (uint32_t)gq * 16)) = w;
    }
    __syncthreads();
    MBAR_WAIT(sb + 64, 0);

    float c[6][4][4];
#pragma unroll
    for (int mi = 0; mi < 6; mi++)
#pragma unroll
        for (int ni = 0; ni < 4; ni++)
#pragma unroll
            for (int q = 0; q < 4; q++) c[mi][ni][q] = 0.f;

    uint32_t lrow = lane & 15, lcg = (uint32_t)(lane >> 4) << 4;
#pragma unroll
    for (int ks = 0; ks < 4; ks++) {
        uint32_t colb = (uint32_t)ks * 32 + lcg;
        uint32_t a[6][4], bf[2][4];
#pragma unroll
        for (int mi = 0; mi < 6; mi++) {
            uint32_t ad = sb + MX_A + SWZ((uint32_t)(wm * 96 + mi * 16 + lrow) * 128 + colb);
            LDSM_X4(a[mi][0], a[mi][1], a[mi][2], a[mi][3], ad);
        }
#pragma unroll
        for (int nj = 0; nj < 2; nj++) {
            uint32_t ad = sb + MX_B + SWZ((uint32_t)(wn * 32 + nj * 16 + lrow) * 128 + colb);
            LDSM_X4(bf[nj][0], bf[nj][1], bf[nj][2], bf[nj][3], ad);
        }
#pragma unroll
        for (int mi = 0; mi < 6; mi++)
#pragma unroll
            for (int ni = 0; ni < 4; ni++)
                MMA16816(c[mi][ni], a[mi], bf[ni >> 1][ni & 1], bf[ni >> 1][(ni & 1) + 2]);
    }

    char* gz = (char*)g_zx;
    uint32_t mt = (uint32_t)(bt >> 1);
    uint32_t rbase = (uint32_t)(bt & 1) << 6;
#pragma unroll
    for (int mi = 0; mi < 6; mi++) {
#pragma unroll
        for (int h = 0; h < 2; h++) {
            uint32_t ko = (uint32_t)(wm * 96 + mi * 16 + h * 8) + (uint32_t)(lane >> 2);
            uint32_t k = ko >> 6, o = ko & 63;
            uint32_t row = rbase + o;
#pragma unroll
            for (int ni = 0; ni < 4; ni++) {
                uint32_t m = (uint32_t)(m0 + wn * 32 + ni * 8) + (uint32_t)((lane & 3) << 1);
                uint32_t kc = k * 64 + (m >> 6);
                __half2 hv = __floats2half2_rn(c[mi][ni][2 * h], c[mi][ni][2 * h + 1]);
                *(uint32_t*)(gz + (((size_t)(mt * KCH + kc)) << 14) +
                             SWZ(row * 128 + ((m & 63) << 1))) = *(uint32_t*)&hv;
            }
        }
    }
}

// ---------------------------------------------------------------------------
// Pass 3: GEMM v2 -- BM=128 BN=128 BK=64, 3 stages (32KB each), 8 consumer
// warps (32x64 warp tile, round-8 burst loop) + 1 producer. 97KB smem/CTA,
// launch_bounds(288,2) -> 2 CTAs/SM, 36 warps (occ ~56%): cross-CTA warp
// interleaving hides LDSM bursts under the other CTA's MMA bursts.
// ---------------------------------------------------------------------------
#define G2_STG 32768
#define G2_NS 3
#define G2_SMEM (1024 + G2_NS * G2_STG)

__global__ void __launch_bounds__(288, 2) gemm_kernel(const float* __restrict__ x,
                                                      const float* __restrict__ bias,
                                                      float* __restrict__ out) {
    extern __shared__ char smem[];
    uint32_t sb = smem_u32(smem);
    int tid = threadIdx.x, lane = tid & 31, wid = tid >> 5;
    int id = blockIdx.x;
    // grouped raster: 6 groups of (8 mt x 32 nt2) = 256 CTAs
    int mt = (id >> 8) * 8 + (id & 7);      // 48 mtiles
    int nt2 = (id >> 3) & 31;               // 32 ntiles of 128 cols

    if (tid == 0) {
#pragma unroll
        for (int s = 0; s < G2_NS; s++) {
            MBAR_INIT(sb + 16 * s, 1);       // full (tx-based)
            MBAR_INIT(sb + 16 * s + 8, 8);   // empty (8 consumer warps)
        }
    }
    FENCE_ASYNC();
    __syncthreads();

    if (wid == 8) {                          // producer warp
        if (lane == 0) {
            const char* As = (const char*)g_zx + ((size_t)mt * KCH << 14);
            // B half-strip: nt2 covers rows [ (nt2&1)*128, ... ) of nt = nt2>>1
            const char* Bs = (const char*)g_bas + ((size_t)(nt2 >> 1) * KCH << 15)
                             + ((size_t)(nt2 & 1) << 14);
            int s = 0, rnd = 0;
            for (int cc = 0; cc < KCH; cc++) {
                if (cc >= G2_NS) MBAR_WAIT(sb + 16 * s + 8, (rnd + 1) & 1);
                MBAR_EXTX(sb + 16 * s, G2_STG);
                uint32_t dst = sb + 1024 + s * G2_STG;
                bulk_g2s(dst, As + ((size_t)cc << 14), 16384, sb + 16 * s);
                bulk_g2s(dst + 16384, Bs + ((size_t)cc << 15), 16384, sb + 16 * s);
                if (++s == G2_NS) { s = 0; rnd ^= 1; }
            }
        }
        return;
    }

    // 8 consumer warps: 4 (wm) x 2 (wn), warp tile 32 rows x 64 cols
    int wm = wid >> 1, wn = wid & 1;
    uint32_t lrow = lane & 15, lcg = (uint32_t)(lane >> 4) << 4;
    uint32_t aoff[2], boff[4];
#pragma unroll
    for (int mi = 0; mi < 2; mi++)
        aoff[mi] = (uint32_t)(wm * 32 + mi * 16 + lrow) * 128;
#pragma unroll
    for (int nj = 0; nj < 4; nj++)
        boff[nj] = 16384u + (uint32_t)(wn * 64 + nj * 16 + lrow) * 128;
    uint32_t swa = ((lrow & 7) << 4);

    float c[2][8][4];
#pragma unroll
    for (int mi = 0; mi < 2; mi++)
#pragma unroll
        for (int ni = 0; ni < 8; ni++)
#pragma unroll
            for (int q = 0; q < 4; q++) c[mi][ni][q] = 0.f;

    int s = 0, rnd = 0;
#pragma unroll 1
    for (int cc = 0; cc < KCH; cc++) {
        MBAR_WAIT(sb + 16 * s, rnd & 1);
        uint32_t stg = sb + 1024 + s * G2_STG;
#pragma unroll
        for (int ks = 0; ks < 4; ks++) {
            uint32_t colb = ((uint32_t)ks * 32 + lcg) ^ swa;
            uint32_t a[2][4], bf[4][4];
#pragma unroll
            for (int mi = 0; mi < 2; mi++)
                LDSM_X4(a[mi][0], a[mi][1], a[mi][2], a[mi][3], stg + aoff[mi] + colb);
#pragma unroll
            for (int nj = 0; nj < 4; nj++)
                LDSM_X4(bf[nj][0], bf[nj][1], bf[nj][2], bf[nj][3], stg + boff[nj] + colb);
#pragma unroll
            for (int mi = 0; mi < 2; mi++)
#pragma unroll
                for (int ni = 0; ni < 8; ni++)
                    MMA16816(c[mi][ni], a[mi], bf[ni >> 1][ni & 1], bf[ni >> 1][(ni & 1) + 2]);
        }
        __syncwarp();
        if (lane == 0) MBAR_ARRIVE(sb + 16 * s + 8);
        if (++s == G2_NS) { s = 0; rnd ^= 1; }
    }

    // fused epilogue: bias + identity residual + relu
#pragma unroll
    for (int mi = 0; mi < 2; mi++) {
#pragma unroll
        for (int h = 0; h < 2; h++) {
            uint32_t r = (uint32_t)(mt * 128 + wm * 32 + mi * 16 + h * 8) + (uint32_t)(lane >> 2);
            uint32_t bt = r >> 6, o = r & 63;
            uint32_t bb = bt / 12, tt = bt - 12 * bb;
            size_t base = ((size_t)((bb << 6) + o) * 12 + tt) * 4096;
            float bv = __ldg(bias + o);
#pragma unroll
            for (int ni = 0; ni < 8; ni++) {
                size_t col = (size_t)(nt2 * 128 + wn * 64 + ni * 8) + ((lane & 3) << 1);
                float2 xv = *(const float2*)(x + base + col);
                float2 ov;
                ov.x = fmaxf(c[mi][ni][2 * h + 0] + bv + xv.x, 0.f);
                ov.y = fmaxf(c[mi][ni][2 * h + 1] + bv + xv.y, 0.f);
                *(float2*)(out + base + col) = ov;
            }
        }
    }
}

// ---------------------------------------------------------------------------
extern "C" void kernel_launch(void* const* d_in, const int* in_sizes, int n_in,
                              void* d_out, int out_size) {
    const float* x = (const float*)d_in[0];
    const float* g = (const float*)d_in[1];
    const float* th = (const float*)d_in[2];
    const float* bias = (const float*)d_in[3];
    float* out = (float*)d_out;

    static cudaStream_t s2 = nullptr;
    static cudaEvent_t ev_fork = nullptr, ev_join = nullptr;
    if (s2 == nullptr) {
        cudaStreamCreateWithFlags(&s2, cudaStreamNonBlocking);
        cudaEventCreateWithFlags(&ev_fork, cudaEventDisableTiming);
        cudaEventCreateWithFlags(&ev_join, cudaEventDisableTiming);
        cudaFuncSetAttribute(gemm_kernel, cudaFuncAttributeMaxDynamicSharedMemorySize, G2_SMEM);
    }

    cudaEventRecord(ev_fork, 0);
    cudaStreamWaitEvent(s2, ev_fork, 0);
    convert_kernel<<<49152, 256, 0, s2>>>(g);
    prep_theta_kernel<<<48, 256>>>(th);
    mix_kernel<<<dim3(96, 32), 256, MX_SMEM>>>(x);
    cudaEventRecord(ev_join, s2);
    cudaStreamWaitEvent(0, ev_join, 0);

    gemm_kernel<<<1536, 288, G2_SMEM>>>(x, bias, out);
}

// round 15
// speedup vs baseline: 1.1507x; 1.0571x over previous
#include <cuda_runtime.h>
#include <cuda_fp16.h>
#include <cstdint>

// out[b,o,t,n] = relu( sum_{i,k,m} theta[i,o,k] x[b,i,t,m] G[k,n,m] + bias[o] + x[b,o,t,n] )
// B=8, C=64, T=12, N=4096, KS=3. r' = bt*64+o in [0,6144). K_total = 3*4096 = 12288 (192 chunks of 64).
// All tensor math via mma.sync (HMMA) -- tcgen05 unavailable (PTX target compute_103, no 'a').

#define KCH 192

// A tiles (Z): [mt 48][kc 192][128 rows x 64 halfs], SW128-swizzled rows. 151 MB.
__device__ __align__(1024) __half g_zx[(size_t)48 * KCH * 8192];
// B tiles (G): [nt 16][kc 192][256 rows x 64 halfs], SW128-swizzled rows. 96 MB.
// (GEMM treats it as 32 half-strips of 128 rows: nt2 = n>>7.)
__device__ __align__(1024) __half g_bas[(size_t)16 * KCH * 16384];
// theta A-tile image: 192 rows x 64 halfs, SW128-swizzled. 24 KB.
__device__ __align__(1024) __half g_tha[192 * 64];

__device__ __forceinline__ uint32_t smem_u32(const void* p) {
    uint32_t a;
    asm("{ .reg .u64 t; cvta.to.shared.u64 t, %1; cvt.u32.u64 %0, t; }" : "=r"(a) : "l"(p));
    return a;
}
#define SWZ(x) ((x) ^ (((x) >> 3) & 0x70u))

#define MBAR_INIT(mb, c) asm volatile("mbarrier.init.shared.b64 [%0], %1;" :: "r"((uint32_t)(mb)), "r"((uint32_t)(c)) : "memory")
#define MBAR_ARRIVE(mb)  asm volatile("mbarrier.arrive.shared.b64 _, [%0];" :: "r"((uint32_t)(mb)) : "memory")
#define MBAR_EXTX(mb, by) asm volatile("mbarrier.arrive.expect_tx.shared.b64 _, [%0], %1;" :: "r"((uint32_t)(mb)), "r"((uint32_t)(by)) : "memory")
#define MBAR_WAIT(mb, ph) do { \
    asm volatile("{\n\t.reg .pred P;\n\tWL%=:\n\t" \
        "mbarrier.try_wait.parity.acquire.cta.shared::cta.b64 P, [%0], %1, 0x989680;\n\t" \
        "@P bra.uni WD%=;\n\tbra.uni WL%=;\n\tWD%=:\n\t}" :: "r"((uint32_t)(mb)), "r"((uint32_t)(ph)) : "memory"); \
} while (0)
#define FENCE_ASYNC() asm volatile("fence.proxy.async.shared::cta;" ::: "memory")

__device__ __forceinline__ void bulk_g2s(uint32_t dst, const void* src, uint32_t bytes, uint32_t mbar) {
    asm volatile("cp.async.bulk.shared::cluster.global.mbarrier::complete_tx::bytes [%0], [%1], %2, [%3];"
                 :: "r"(dst), "l"(src), "r"(bytes), "r"(mbar) : "memory");
}

#define LDSM_X4(r0, r1, r2, r3, addr) \
    asm volatile("ldmatrix.sync.aligned.m8n8.x4.shared.b16 {%0,%1,%2,%3}, [%4];" \
                 : "=r"(r0), "=r"(r1), "=r"(r2), "=r"(r3) : "r"(addr))

#define MMA16816(c, a, b0_, b1_) \
    asm volatile("mma.sync.aligned.m16n8k16.row.col.f32.f16.f16.f32 " \
                 "{%0,%1,%2,%3}, {%4,%5,%6,%7}, {%8,%9}, {%0,%1,%2,%3};" \
                 : "+f"((c)[0]), "+f"((c)[1]), "+f"((c)[2]), "+f"((c)[3]) \
                 : "r"((a)[0]), "r"((a)[1]), "r"((a)[2]), "r"((a)[3]), "r"(b0_), "r"(b1_))

// ---------------------------------------------------------------------------
// Pass 1a: G fp32 [k][n][m] -> fp16 pre-swizzled B tiles (standalone).
// ---------------------------------------------------------------------------
__global__ void __launch_bounds__(256) convert_kernel(const float* __restrict__ g) {
    size_t e = ((size_t)blockIdx.x * 256 + threadIdx.x) << 2;
    float4 v = *(const float4*)(g + e);
    uint32_t m = (uint32_t)(e & 4095), n = (uint32_t)((e >> 12) & 4095), k = (uint32_t)(e >> 24);
    uint32_t kc = (k << 6) + (m >> 6);
    uint32_t off = SWZ(((n & 255) << 7) + ((m & 63) << 1));
    __half2 h0 = __floats2half2_rn(v.x, v.y), h1 = __floats2half2_rn(v.z, v.w);
    uint2 w = make_uint2(*(uint32_t*)&h0, *(uint32_t*)&h1);
    *(uint2*)((char*)g_bas + (((size_t)((n >> 8) * KCH + kc)) << 15) + off) = w;
}

// ---------------------------------------------------------------------------
// Pass 1b: theta[i][o][k] -> A-tile image (rows k*64+o, col i, SW128). Tiny.
// ---------------------------------------------------------------------------
__global__ void __launch_bounds__(256) prep_theta_kernel(const float* __restrict__ th) {
    int e = blockIdx.x * 256 + threadIdx.x;          // 12288 elements, grid 48
    int k = e % 3, io = e / 3;
    int o = io & 63, i = io >> 6;
    *(__half*)((char*)g_tha + SWZ((uint32_t)(k * 64 + o) * 128 + (uint32_t)i * 2)) =
        __float2half_rn(th[e]);
}

// ---------------------------------------------------------------------------
// Pass 2: theta-mix. CTA = (bt, 128-wide m chunk). 256 threads, 8 warps (2M x 4N).
// ---------------------------------------------------------------------------
#define MX_A 1024
#define MX_B (1024 + 24576)
#define MX_SMEM (1024 + 24576 + 16384)

__global__ void __launch_bounds__(256) mix_kernel(const float* __restrict__ x) {
    extern __shared__ char smem[];
    uint32_t sb = smem_u32(smem);
    int tid = threadIdx.x, lane = tid & 31, wid = tid >> 5;
    int wm = wid >> 2, wn = wid & 3;
    int bt = blockIdx.x, m0 = blockIdx.y << 7;
    int b = bt / 12, t = bt - 12 * b;

    if (tid == 0) MBAR_INIT(sb + 64, 1);
    FENCE_ASYNC();
    __syncthreads();
    if (tid == 0) {                               // theta tile: one bulk copy
        MBAR_EXTX(sb + 64, 24576);
        bulk_g2s(sb + MX_A, g_tha, 24576, sb + 64);
    }

    const float* xb = x + ((size_t)b * 768 + t) * 4096 + m0;
#pragma unroll
    for (int it = 0; it < 4; it++) {
        int idx = tid + it * 256;
        int m = idx & 127, gq = idx >> 7;
        float v[8];
#pragma unroll
        for (int di = 0; di < 8; di++)
            v[di] = xb[(size_t)(gq * 8 + di) * 49152 + m];
        __half2 h0 = __floats2half2_rn(v[0], v[1]);
        __half2 h1 = __floats2half2_rn(v[2], v[3]);
        __half2 h2 = __floats2half2_rn(v[4], v[5]);
        __half2 h3 = __floats2half2_rn(v[6], v[7]);
        uint4 w = make_uint4(*(uint32_t*)&h0, *(uint32_t*)&h1,
                             *(uint32_t*)&h2, *(uint32_t*)&h3);
        *(uint4*)(smem + MX_B + SWZ((uint32_t)m * 128 + (uint32_t)gq * 16)) = w;
    }
    __syncthreads();
    MBAR_WAIT(sb + 64, 0);

    float c[6][4][4];
#pragma unroll
    for (int mi = 0; mi < 6; mi++)
#pragma unroll
        for (int ni = 0; ni < 4; ni++)
#pragma unroll
            for (int q = 0; q < 4; q++) c[mi][ni][q] = 0.f;

    uint32_t lrow = lane & 15, lcg = (uint32_t)(lane >> 4) << 4;
#pragma unroll
    for (int ks = 0; ks < 4; ks++) {
        uint32_t colb = (uint32_t)ks * 32 + lcg;
        uint32_t a[6][4], bf[2][4];
#pragma unroll
        for (int mi = 0; mi < 6; mi++) {
            uint32_t ad = sb + MX_A + SWZ((uint32_t)(wm * 96 + mi * 16 + lrow) * 128 + colb);
            LDSM_X4(a[mi][0], a[mi][1], a[mi][2], a[mi][3], ad);
        }
#pragma unroll
        for (int nj = 0; nj < 2; nj++) {
            uint32_t ad = sb + MX_B + SWZ((uint32_t)(wn * 32 + nj * 16 + lrow) * 128 + colb);
            LDSM_X4(bf[nj][0], bf[nj][1], bf[nj][2], bf[nj][3], ad);
        }
#pragma unroll
        for (int mi = 0; mi < 6; mi++)
#pragma unroll
            for (int ni = 0; ni < 4; ni++)
                MMA16816(c[mi][ni], a[mi], bf[ni >> 1][ni & 1], bf[ni >> 1][(ni & 1) + 2]);
    }

    char* gz = (char*)g_zx;
    uint32_t mt = (uint32_t)(bt >> 1);
    uint32_t rbase = (uint32_t)(bt & 1) << 6;
#pragma unroll
    for (int mi = 0; mi < 6; mi++) {
#pragma unroll
        for (int h = 0; h < 2; h++) {
            uint32_t ko = (uint32_t)(wm * 96 + mi * 16 + h * 8) + (uint32_t)(lane >> 2);
            uint32_t k = ko >> 6, o = ko & 63;
            uint32_t row = rbase + o;
#pragma unroll
            for (int ni = 0; ni < 4; ni++) {
                uint32_t m = (uint32_t)(m0 + wn * 32 + ni * 8) + (uint32_t)((lane & 3) << 1);
                uint32_t kc = k * 64 + (m >> 6);
                __half2 hv = __floats2half2_rn(c[mi][ni][2 * h], c[mi][ni][2 * h + 1]);
                *(uint32_t*)(gz + (((size_t)(mt * KCH + kc)) << 14) +
                             SWZ(row * 128 + ((m & 63) << 1))) = *(uint32_t*)&hv;
            }
        }
    }
}

// ---------------------------------------------------------------------------
// Pass 3: GEMM -- BM=128 BN=128 BK=64, 3 stages (32KB), 8 consumer warps
// (32x64 warp tile) + 1 producer, 2 CTAs/SM. Chunk loop unrolled by 3 so all
// stage indices / mbarrier addresses / parities are compile-time constants.
// ---------------------------------------------------------------------------
#define G2_STG 32768
#define G2_NS 3
#define G2_SMEM (1024 + G2_NS * G2_STG)

__global__ void __launch_bounds__(288, 2) gemm_kernel(const float* __restrict__ x,
                                                      const float* __restrict__ bias,
                                                      float* __restrict__ out) {
    extern __shared__ char smem[];
    uint32_t sb = smem_u32(smem);
    int tid = threadIdx.x, lane = tid & 31, wid = tid >> 5;
    int id = blockIdx.x;
    // grouped raster: 6 groups of (8 mt x 32 nt2) = 256 CTAs
    int mt = (id >> 8) * 8 + (id & 7);      // 48 mtiles
    int nt2 = (id >> 3) & 31;               // 32 ntiles of 128 cols

    if (tid == 0) {
#pragma unroll
        for (int s = 0; s < G2_NS; s++) {
            MBAR_INIT(sb + 16 * s, 1);       // full (tx-based)
            MBAR_INIT(sb + 16 * s + 8, 8);   // empty (8 consumer warps)
        }
    }
    FENCE_ASYNC();
    __syncthreads();

    if (wid == 8) {                          // producer warp
        if (lane == 0) {
            const char* As = (const char*)g_zx + ((size_t)mt * KCH << 14);
            const char* Bs = (const char*)g_bas + ((size_t)(nt2 >> 1) * KCH << 15)
                             + ((size_t)(nt2 & 1) << 14);
            int s = 0, rnd = 0;
            for (int cc = 0; cc < KCH; cc++) {
                if (cc >= G2_NS) MBAR_WAIT(sb + 16 * s + 8, (rnd + 1) & 1);
                MBAR_EXTX(sb + 16 * s, G2_STG);
                uint32_t dst = sb + 1024 + s * G2_STG;
                bulk_g2s(dst, As + ((size_t)cc << 14), 16384, sb + 16 * s);
                bulk_g2s(dst + 16384, Bs + ((size_t)cc << 15), 16384, sb + 16 * s);
                if (++s == G2_NS) { s = 0; rnd ^= 1; }
            }
        }
        return;
    }

    // 8 consumer warps: 4 (wm) x 2 (wn), warp tile 32 rows x 64 cols
    int wm = wid >> 1, wn = wid & 1;
    uint32_t lrow = lane & 15, lcg = (uint32_t)(lane >> 4) << 4;
    uint32_t aoff[2], boff[4];
#pragma unroll
    for (int mi = 0; mi < 2; mi++)
        aoff[mi] = (uint32_t)(wm * 32 + mi * 16 + lrow) * 128;
#pragma unroll
    for (int nj = 0; nj < 4; nj++)
        boff[nj] = 16384u + (uint32_t)(wn * 64 + nj * 16 + lrow) * 128;
    uint32_t swa = ((lrow & 7) << 4);

    float c[2][8][4];
#pragma unroll
    for (int mi = 0; mi < 2; mi++)
#pragma unroll
        for (int ni = 0; ni < 8; ni++)
#pragma unroll
            for (int q = 0; q < 4; q++) c[mi][ni][q] = 0.f;

    // one chunk with compile-time stage S and parity PH
#define CHUNK_BODY(S, PH) do { \
    MBAR_WAIT(sb + 16 * (S), (PH)); \
    const uint32_t stg = sb + 1024 + (S) * G2_STG; \
    _Pragma("unroll") \
    for (int ks = 0; ks < 4; ks++) { \
        uint32_t colb = ((uint32_t)ks * 32 + lcg) ^ swa; \
        uint32_t a[2][4], bf[4][4]; \
        _Pragma("unroll") \
        for (int mi = 0; mi < 2; mi++) \
            LDSM_X4(a[mi][0], a[mi][1], a[mi][2], a[mi][3], stg + aoff[mi] + colb); \
        _Pragma("unroll") \
        for (int nj = 0; nj < 4; nj++) \
            LDSM_X4(bf[nj][0], bf[nj][1], bf[nj][2], bf[nj][3], stg + boff[nj] + colb); \
        if (ks == 3 && lane == 0) MBAR_ARRIVE(sb + 16 * (S) + 8); \
        _Pragma("unroll") \
        for (int mi = 0; mi < 2; mi++) \
            _Pragma("unroll") \
            for (int ni = 0; ni < 8; ni++) \
                MMA16816(c[mi][ni], a[mi], bf[ni >> 1][ni & 1], bf[ni >> 1][(ni & 1) + 2]); \
    } \
} while (0)

#pragma unroll 1
    for (int trip = 0; trip < KCH / (2 * G2_NS); trip++) {   // 32 trips x 6 chunks
        CHUNK_BODY(0, 0); CHUNK_BODY(1, 0); CHUNK_BODY(2, 0);
        CHUNK_BODY(0, 1); CHUNK_BODY(1, 1); CHUNK_BODY(2, 1);
    }
#undef CHUNK_BODY

    // fused epilogue: bias + identity residual + relu
#pragma unroll
    for (int mi = 0; mi < 2; mi++) {
#pragma unroll
        for (int h = 0; h < 2; h++) {
            uint32_t r = (uint32_t)(mt * 128 + wm * 32 + mi * 16 + h * 8) + (uint32_t)(lane >> 2);
            uint32_t bt = r >> 6, o = r & 63;
            uint32_t bb = bt / 12, tt = bt - 12 * bb;
            size_t base = ((size_t)((bb << 6) + o) * 12 + tt) * 4096;
            float bv = __ldg(bias + o);
#pragma unroll
            for (int ni = 0; ni < 8; ni++) {
                size_t col = (size_t)(nt2 * 128 + wn * 64 + ni * 8) + ((lane & 3) << 1);
                float2 xv = *(const float2*)(x + base + col);
                float2 ov;
                ov.x = fmaxf(c[mi][ni][2 * h + 0] + bv + xv.x, 0.f);
                ov.y = fmaxf(c[mi][ni][2 * h + 1] + bv + xv.y, 0.f);
                *(float2*)(out + base + col) = ov;
            }
        }
    }
}

// ---------------------------------------------------------------------------
extern "C" void kernel_launch(void* const* d_in, const int* in_sizes, int n_in,
                              void* d_out, int out_size) {
    const float* x = (const float*)d_in[0];
    const float* g = (const float*)d_in[1];
    const float* th = (const float*)d_in[2];
    const float* bias = (const float*)d_in[3];
    float* out = (float*)d_out;

    static cudaStream_t s2 = nullptr;
    static cudaEvent_t ev_fork = nullptr, ev_join = nullptr;
    if (s2 == nullptr) {
        cudaStreamCreateWithFlags(&s2, cudaStreamNonBlocking);
        cudaEventCreateWithFlags(&ev_fork, cudaEventDisableTiming);
        cudaEventCreateWithFlags(&ev_join, cudaEventDisableTiming);
        cudaFuncSetAttribute(gemm_kernel, cudaFuncAttributeMaxDynamicSharedMemorySize, G2_SMEM);
    }

    cudaEventRecord(ev_fork, 0);
    cudaStreamWaitEvent(s2, ev_fork, 0);
    convert_kernel<<<49152, 256, 0, s2>>>(g);
    prep_theta_kernel<<<48, 256>>>(th);
    mix_kernel<<<dim3(96, 32), 256, MX_SMEM>>>(x);
    cudaEventRecord(ev_join, s2);
    cudaStreamWaitEvent(0, ev_join, 0);

    gemm_kernel<<<1536, 288, G2_SMEM>>>(x, bias, out);
}